// round 1
// baseline (speedup 1.0000x reference)
#include <cuda_runtime.h>
#include <math.h>

// ---------------- problem constants ----------------
constexpr int WID    = 512;
constexpr int SEQL   = 1752;
constexpr int BLK    = 146;   // 128 frame + delim + 16 dyn + delim
constexpr int NFR    = 12;    // N frames (13-1)
constexpr int NB     = 4;     // batch
constexpr int NH     = 8;     // heads
constexpr int NLAYER = 6;
constexpr int MROWS  = NB * SEQL;        // 7008
constexpr int MPAD   = 7040;             // padded to /128
constexpr int MHEAD  = NB * NFR * 128;   // 6144 logit rows

// ---------------- scratch (device globals; no cudaMalloc allowed) ----------------
__device__ float g_h  [(size_t)MPAD * WID];
__device__ float g_a  [(size_t)MPAD * WID];
__device__ float g_qkv[(size_t)MPAD * 3 * WID];
__device__ float g_o  [(size_t)MPAD * WID];
__device__ float g_mlp[(size_t)MPAD * 4 * WID];
__device__ float g_hf [(size_t)MHEAD * WID];

// ---------------- build h = concat(x, delim, f, delim) + pos_emb ----------------
__global__ void build_h_kernel(const float* __restrict__ x, const float* __restrict__ f,
                               const float* __restrict__ delim) {
  __shared__ float rden[256];
  int tid = threadIdx.x;  // 256 threads
  // 1/denom computed in double for accuracy (i2 = tid)
  rden[tid] = (float)(1.0 / pow(10000.0, (double)tid / 256.0));
  __syncthreads();
  int row = blockIdx.x;
  float* hr = g_h + (size_t)row * WID;
  if (row >= MROWS) {  // zero the pad rows (stay zero forever)
    hr[tid] = 0.f; hr[tid + 256] = 0.f;
    return;
  }
  int b = row / SEQL, s = row % SEQL;
  int fi = s / BLK, r = s - fi * BLK;
  const float* src;
  if (r < 128)                    src = x + (size_t)((b * NFR + fi) * 128 + r) * WID;
  else if (r == 128 || r == 145)  src = delim;
  else                            src = f + (size_t)(b * NFR * 16 + fi * 16 + (r - 129)) * WID;
#pragma unroll
  for (int c = tid; c < WID; c += 256) {
    float ang = (float)s * rden[c >> 1];
    float p = (c & 1) ? cosf(ang) : sinf(ang);
    hr[c] = src[c] + p;
  }
}

// ---------------- LayerNorm: one block per row ----------------
__global__ void ln_kernel(const float* __restrict__ X, const float* __restrict__ sc,
                          const float* __restrict__ bi, float* __restrict__ Y) {
  int row = blockIdx.x;
  const float* xr = X + (size_t)row * WID;
  int tid = threadIdx.x;  // 256
  float v0 = xr[tid], v1 = xr[tid + 256];
  float s = v0 + v1, q = v0 * v0 + v1 * v1;
#pragma unroll
  for (int o = 16; o; o >>= 1) {
    s += __shfl_xor_sync(0xffffffffu, s, o);
    q += __shfl_xor_sync(0xffffffffu, q, o);
  }
  __shared__ float ss[8], sq[8];
  if ((tid & 31) == 0) { ss[tid >> 5] = s; sq[tid >> 5] = q; }
  __syncthreads();
  float ts = 0.f, tq = 0.f;
#pragma unroll
  for (int k = 0; k < 8; k++) { ts += ss[k]; tq += sq[k]; }
  float mu = ts * (1.f / WID);
  float var = tq * (1.f / WID) - mu * mu;
  float rstd = rsqrtf(var + 1e-5f);
  float* yr = Y + (size_t)row * WID;
  yr[tid]       = (v0 - mu) * rstd * sc[tid]       + bi[tid];
  yr[tid + 256] = (v1 - mu) * rstd * sc[tid + 256] + bi[tid + 256];
}

// ---------------- SGEMM (NT): C[m,n] = sum_k A[m,k]*B[n,k], 128x128x16 tiles ----------------
// EPI: 0 none, 1 +bias, 2 +bias->gelu, 3 +bias+residual
template <int EPI>
__global__ __launch_bounds__(256, 2) void gemm128(
    const float* __restrict__ A, const float* __restrict__ Bw,
    const float* __restrict__ bias, const float* __restrict__ Res,
    float* __restrict__ C, int N, int K) {
  __shared__ __align__(16) float As[16][132];
  __shared__ __align__(16) float Bs[16][132];
  const int bm = blockIdx.y * 128;
  const int bn = blockIdx.x * 128;
  const int tid = threadIdx.x;
  const int tx = tid & 15, ty = tid >> 4;
  const int lr = tid >> 2;          // 0..63
  const int lk = (tid & 3) << 2;    // 0,4,8,12
  const float* Ag = A + (size_t)(bm + lr) * K + lk;
  const float* Bg = Bw + (size_t)(bn + lr) * K + lk;
  float acc[8][8];
#pragma unroll
  for (int i = 0; i < 8; i++)
#pragma unroll
    for (int j = 0; j < 8; j++) acc[i][j] = 0.f;

  for (int k0 = 0; k0 < K; k0 += 16) {
    float4 a0 = *(const float4*)(Ag + k0);
    float4 a1 = *(const float4*)(Ag + (size_t)64 * K + k0);
    float4 b0 = *(const float4*)(Bg + k0);
    float4 b1 = *(const float4*)(Bg + (size_t)64 * K + k0);
    As[lk + 0][lr] = a0.x; As[lk + 1][lr] = a0.y; As[lk + 2][lr] = a0.z; As[lk + 3][lr] = a0.w;
    As[lk + 0][lr + 64] = a1.x; As[lk + 1][lr + 64] = a1.y; As[lk + 2][lr + 64] = a1.z; As[lk + 3][lr + 64] = a1.w;
    Bs[lk + 0][lr] = b0.x; Bs[lk + 1][lr] = b0.y; Bs[lk + 2][lr] = b0.z; Bs[lk + 3][lr] = b0.w;
    Bs[lk + 0][lr + 64] = b1.x; Bs[lk + 1][lr + 64] = b1.y; Bs[lk + 2][lr + 64] = b1.z; Bs[lk + 3][lr + 64] = b1.w;
    __syncthreads();
#pragma unroll
    for (int kk = 0; kk < 16; kk++) {
      float ar[8], br[8];
      *(float4*)(ar)     = *(const float4*)(&As[kk][ty * 8]);
      *(float4*)(ar + 4) = *(const float4*)(&As[kk][ty * 8 + 4]);
      *(float4*)(br)     = *(const float4*)(&Bs[kk][tx * 8]);
      *(float4*)(br + 4) = *(const float4*)(&Bs[kk][tx * 8 + 4]);
#pragma unroll
      for (int i = 0; i < 8; i++)
#pragma unroll
        for (int j = 0; j < 8; j++) acc[i][j] = fmaf(ar[i], br[j], acc[i][j]);
    }
    __syncthreads();
  }
#pragma unroll
  for (int i = 0; i < 8; i++) {
    int m = bm + ty * 8 + i;
    float* crow = C + (size_t)m * N + bn + tx * 8;
    const float* rrow = (EPI == 3) ? (Res + (size_t)m * N + bn + tx * 8) : nullptr;
#pragma unroll
    for (int j = 0; j < 8; j++) {
      float v = acc[i][j];
      if (EPI >= 1) v += bias[bn + tx * 8 + j];
      if (EPI == 2) v = 0.5f * v * (1.f + erff(v * 0.70710678118654752f));
      if (EPI == 3) v += rrow[j];
      crow[j] = v;
    }
  }
}

// ---------------- structured attention ----------------
// Frame-token rows of frame i attend to: same-frame 128 tokens,
// position fs-1 (i>0), and {j*BLK+128 .. +144} for j<=i. Uniform mask across the
// whole frame -> flash-style streaming over a gathered key list (<=333 keys).
// grid: x = frame*2 + qhalf (24), y = head (8), z = batch (4); 256 threads.
__global__ __launch_bounds__(256) void attn_kernel(const float* __restrict__ qkv,
                                                   float* __restrict__ O) {
  const int fi = blockIdx.x >> 1, qt = blockIdx.x & 1;
  const int h = blockIdx.y, b = blockIdx.z;
  const int fs = fi * BLK;
  const int q0 = fs + qt * 64;
  const int nE = (fi > 0) ? (1 + 17 * (fi + 1)) : 17;
  const int nK = 128 + nE;
  const float* base = qkv + (size_t)b * SEQL * 1536;

  __shared__ __align__(16) float Qs[64][68];  // [d][q], pre-scaled
  __shared__ __align__(16) float Ks[64][36];  // [d][k]
  __shared__ __align__(16) float Vs[32][68];  // [k][d]
  __shared__ __align__(16) float Ps[32][68];  // [k][q] scores/probs transposed
  __shared__ float m_s[64], l_s[64], al_s[64];

  const int tid = threadIdx.x;
  {  // load Q tile (64 rows x 64 d), scaled by dh^-0.5 = 0.125
    int qr = tid >> 2;
    int c4 = tid & 3;
    const float* qrow = base + (size_t)(q0 + qr) * 1536 + h * 64;
#pragma unroll
    for (int j = 0; j < 4; j++) {
      int d = (c4 * 4 + j) * 4;
      float4 v = *(const float4*)(qrow + d);
      Qs[d + 0][qr] = v.x * 0.125f; Qs[d + 1][qr] = v.y * 0.125f;
      Qs[d + 2][qr] = v.z * 0.125f; Qs[d + 3][qr] = v.w * 0.125f;
    }
  }
  if (tid < 64) { m_s[tid] = -1e30f; l_s[tid] = 0.f; }

  const int tx = tid & 15, ty = tid >> 4;
  float Oa[4][4];
#pragma unroll
  for (int i = 0; i < 4; i++)
#pragma unroll
    for (int j = 0; j < 4; j++) Oa[i][j] = 0.f;

  const int nCh = (nK + 31) / 32;
  for (int ch = 0; ch < nCh; ch++) {
    const int kb = ch * 32;
    __syncthreads();  // Q visible (1st iter) / Ps,Vs consumed (later iters)
    {  // load K,V chunk of 32 gathered rows
      int kr = tid >> 3;
      int c2 = tid & 7;
      int t = kb + kr;
      int pos;
      if (t >= nK) pos = fs;              // masked tail, any valid row
      else if (t < 128) pos = fs + t;     // same-frame tokens
      else {
        int e = t - 128;
        if (fi > 0) {
          if (e == 0) pos = fs - 1;       // prev frame's final delim
          else { int e2 = e - 1; pos = (e2 / 17) * BLK + 128 + (e2 % 17); }
        } else pos = 128 + e;             // frame 0: own delim+dynamics
      }
      const float* krow = base + (size_t)pos * 1536 + 512 + h * 64;
      const float* vrow = base + (size_t)pos * 1536 + 1024 + h * 64;
#pragma unroll
      for (int j = 0; j < 2; j++) {
        int d = (c2 * 2 + j) * 4;
        float4 kv = *(const float4*)(krow + d);
        Ks[d + 0][kr] = kv.x; Ks[d + 1][kr] = kv.y; Ks[d + 2][kr] = kv.z; Ks[d + 3][kr] = kv.w;
        float4 vv = *(const float4*)(vrow + d);
        *(float4*)(&Vs[kr][d]) = vv;
      }
    }
    __syncthreads();
    // scores S[q=ty*4+i][k=tx*2+j]
    float sreg[4][2];
#pragma unroll
    for (int i = 0; i < 4; i++) { sreg[i][0] = 0.f; sreg[i][1] = 0.f; }
#pragma unroll
    for (int d = 0; d < 64; d++) {
      float qv[4];
      *(float4*)qv = *(const float4*)(&Qs[d][ty * 4]);
      float k0 = Ks[d][tx * 2], k1 = Ks[d][tx * 2 + 1];
#pragma unroll
      for (int i = 0; i < 4; i++) {
        sreg[i][0] = fmaf(qv[i], k0, sreg[i][0]);
        sreg[i][1] = fmaf(qv[i], k1, sreg[i][1]);
      }
    }
#pragma unroll
    for (int j = 0; j < 2; j++) {
      int t = kb + tx * 2 + j;
      bool valid = (t < nK);
#pragma unroll
      for (int i = 0; i < 4; i++)
        Ps[tx * 2 + j][ty * 4 + i] = valid ? sreg[i][j] : -1e30f;
    }
    __syncthreads();
    // online softmax: thread r owns q-row r
    if (tid < 64) {
      float mo = m_s[tid];
      float mc = -1e30f;
#pragma unroll
      for (int kk = 0; kk < 32; kk++) mc = fmaxf(mc, Ps[kk][tid]);
      float mn = fmaxf(mo, mc);
      float al = expf(mo - mn);
      float ls = 0.f;
#pragma unroll
      for (int kk = 0; kk < 32; kk++) {
        float p = expf(Ps[kk][tid] - mn);
        Ps[kk][tid] = p;
        ls += p;
      }
      m_s[tid] = mn;
      l_s[tid] = l_s[tid] * al + ls;
      al_s[tid] = al;
    }
    __syncthreads();
    // O = O*alpha + P@V  (O tile 64q x 64d, thread 4x4)
#pragma unroll
    for (int i = 0; i < 4; i++) {
      float al = al_s[ty * 4 + i];
#pragma unroll
      for (int j = 0; j < 4; j++) Oa[i][j] *= al;
    }
#pragma unroll
    for (int kk = 0; kk < 32; kk++) {
      float pr[4], vr[4];
      *(float4*)pr = *(const float4*)(&Ps[kk][ty * 4]);
      *(float4*)vr = *(const float4*)(&Vs[kk][tx * 4]);
#pragma unroll
      for (int i = 0; i < 4; i++)
#pragma unroll
        for (int j = 0; j < 4; j++) Oa[i][j] = fmaf(pr[i], vr[j], Oa[i][j]);
    }
  }
  // write out (l_s final; synced before last O update)
#pragma unroll
  for (int i = 0; i < 4; i++) {
    int q = ty * 4 + i;
    float inv = 1.f / l_s[q];
    float* orow = O + (size_t)(b * SEQL + q0 + q) * WID + h * 64 + tx * 4;
    float4 ov = make_float4(Oa[i][0] * inv, Oa[i][1] * inv, Oa[i][2] * inv, Oa[i][3] * inv);
    *(float4*)orow = ov;
  }
}

// ---------------- non-frame rows: attention output == V (self-only mask) ----------------
__global__ void copyv_kernel() {
  int idx = blockIdx.x * 256 + threadIdx.x;  // NB*NFR*18*512
  if (idx >= NB * NFR * 18 * WID) return;
  int c = idx & 511;
  int rid = idx >> 9;
  int b = rid / (NFR * 18);
  int rr = rid % (NFR * 18);
  int fi = rr / 18, r = 128 + rr % 18;
  size_t srow = (size_t)b * SEQL + fi * BLK + r;
  g_o[srow * WID + c] = g_qkv[srow * 1536 + 1024 + c];
}

// ---------------- gather frame-token rows for the prediction head ----------------
__global__ void gather_kernel() {
  int idx = blockIdx.x * 256 + threadIdx.x;  // MHEAD*512
  if (idx >= MHEAD * WID) return;
  int c = idx & 511, rid = idx >> 9;
  int b = rid / 1536, m = rid % 1536;
  int s = (m >> 7) * BLK + (m & 127);
  g_hf[(size_t)rid * WID + c] = g_h[(size_t)(b * SEQL + s) * WID + c];
}

// ---------------- launch ----------------
extern "C" void kernel_launch(void* const* d_in, const int* in_sizes, int n_in,
                              void* d_out, int out_size) {
  const float* x     = (const float*)d_in[0];
  const float* f     = (const float*)d_in[1];
  const float* delim = (const float*)d_in[2];
  const float* ln1s  = (const float*)d_in[3];
  const float* ln1b  = (const float*)d_in[4];
  const float* wqkv  = (const float*)d_in[5];
  const float* bqkv  = (const float*)d_in[6];
  const float* wout  = (const float*)d_in[7];
  const float* bout  = (const float*)d_in[8];
  const float* ln2s  = (const float*)d_in[9];
  const float* ln2b  = (const float*)d_in[10];
  const float* wfc   = (const float*)d_in[11];
  const float* bfc   = (const float*)d_in[12];
  const float* wproj = (const float*)d_in[13];
  const float* bproj = (const float*)d_in[14];
  const float* whead = (const float*)d_in[15];
  float* out = (float*)d_out;

  float *h, *a, *qkv, *o, *mlp, *hf;
  cudaGetSymbolAddress((void**)&h, g_h);
  cudaGetSymbolAddress((void**)&a, g_a);
  cudaGetSymbolAddress((void**)&qkv, g_qkv);
  cudaGetSymbolAddress((void**)&o, g_o);
  cudaGetSymbolAddress((void**)&mlp, g_mlp);
  cudaGetSymbolAddress((void**)&hf, g_hf);

  build_h_kernel<<<MPAD, 256>>>(x, f, delim);

  for (int l = 0; l < NLAYER; l++) {
    ln_kernel<<<MROWS, 256>>>(h, ln1s + l * WID, ln1b + l * WID, a);
    gemm128<1><<<dim3(1536 / 128, MPAD / 128), 256>>>(
        a, wqkv + (size_t)l * 1536 * WID, bqkv + l * 1536, nullptr, qkv, 1536, WID);
    attn_kernel<<<dim3(NFR * 2, NH, NB), 256>>>(qkv, o);
    copyv_kernel<<<(NB * NFR * 18 * WID + 255) / 256, 256>>>();
    gemm128<3><<<dim3(WID / 128, MPAD / 128), 256>>>(
        o, wout + (size_t)l * WID * WID, bout + l * WID, h, h, WID, WID);
    ln_kernel<<<MROWS, 256>>>(h, ln2s + l * WID, ln2b + l * WID, a);
    gemm128<2><<<dim3(2048 / 128, MPAD / 128), 256>>>(
        a, wfc + (size_t)l * 2048 * WID, bfc + l * 2048, nullptr, mlp, 2048, WID);
    gemm128<3><<<dim3(WID / 128, MPAD / 128), 256>>>(
        mlp, wproj + (size_t)l * WID * 2048, bproj + l * WID, h, h, WID, 2048);
  }

  gather_kernel<<<(MHEAD * WID + 255) / 256, 256>>>();
  gemm128<0><<<dim3(1024 / 128, MHEAD / 128), 256>>>(
      hf, whead, nullptr, nullptr, out, 1024, WID);
}

// round 6
// speedup vs baseline: 1.8239x; 1.8239x over previous
#include <cuda_runtime.h>
#include <stdint.h>
#include <math.h>

// ---------------- problem constants ----------------
constexpr int WID    = 512;
constexpr int SEQL   = 1752;
constexpr int BLK    = 146;   // 128 frame + delim + 16 dyn + delim
constexpr int NFR    = 12;    // N frames (13-1)
constexpr int NB     = 4;     // batch
constexpr int NH     = 8;     // heads
constexpr int NLAYER = 6;
constexpr int MROWS  = NB * SEQL;        // 7008
constexpr int MPAD   = 7040;             // padded to /128
constexpr int MHEAD  = NB * NFR * 128;   // 6144 logit rows

// ---------------- scratch (device globals; no cudaMalloc allowed) ----------------
__device__ float g_h  [(size_t)MPAD * WID];
__device__ float g_a  [(size_t)MPAD * WID];
__device__ float g_qkv[(size_t)MPAD * 3 * WID];
__device__ float g_o  [(size_t)MPAD * WID];
__device__ float g_mlp[(size_t)MPAD * 4 * WID];
__device__ float g_hf [(size_t)MHEAD * WID];

// ---------------- helpers ----------------
__device__ __forceinline__ float ftf32(float x) {
  unsigned int u = __float_as_uint(x), r;
  asm("cvt.rna.tf32.f32 %0, %1;" : "=r"(r) : "r"(u));
  return __uint_as_float(r);
}

__device__ __forceinline__ void mma_tf32(float* d, const float* a, const float* b) {
  asm volatile(
      "mma.sync.aligned.m16n8k8.row.col.f32.tf32.tf32.f32 "
      "{%0,%1,%2,%3}, {%4,%5,%6,%7}, {%8,%9}, {%0,%1,%2,%3};"
      : "+f"(d[0]), "+f"(d[1]), "+f"(d[2]), "+f"(d[3])
      : "r"(__float_as_uint(a[0])), "r"(__float_as_uint(a[1])),
        "r"(__float_as_uint(a[2])), "r"(__float_as_uint(a[3])),
        "r"(__float_as_uint(b[0])), "r"(__float_as_uint(b[1])));
}

// ---------------- build h = concat(x, delim, f, delim) + pos_emb ----------------
__global__ void build_h_kernel(const float* __restrict__ x, const float* __restrict__ f,
                               const float* __restrict__ delim) {
  __shared__ float rden[256];
  int tid = threadIdx.x;  // 256 threads
  rden[tid] = (float)(1.0 / pow(10000.0, (double)tid / 256.0));
  __syncthreads();
  int row = blockIdx.x;
  float* hr = g_h + (size_t)row * WID;
  if (row >= MROWS) { hr[tid] = 0.f; hr[tid + 256] = 0.f; return; }
  int b = row / SEQL, s = row % SEQL;
  int fi = s / BLK, r = s - fi * BLK;
  const float* src;
  if (r < 128)                    src = x + (size_t)((b * NFR + fi) * 128 + r) * WID;
  else if (r == 128 || r == 145)  src = delim;
  else                            src = f + (size_t)(b * NFR * 16 + fi * 16 + (r - 129)) * WID;
#pragma unroll
  for (int c = tid; c < WID; c += 256) {
    float ang = (float)s * rden[c >> 1];
    float p = (c & 1) ? cosf(ang) : sinf(ang);
    hr[c] = src[c] + p;
  }
}

// ---------------- LayerNorm: one block per row ----------------
__global__ void ln_kernel(const float* __restrict__ X, const float* __restrict__ sc,
                          const float* __restrict__ bi, float* __restrict__ Y) {
  int row = blockIdx.x;
  const float* xr = X + (size_t)row * WID;
  int tid = threadIdx.x;  // 256
  float v0 = xr[tid], v1 = xr[tid + 256];
  float s = v0 + v1, q = v0 * v0 + v1 * v1;
#pragma unroll
  for (int o = 16; o; o >>= 1) {
    s += __shfl_xor_sync(0xffffffffu, s, o);
    q += __shfl_xor_sync(0xffffffffu, q, o);
  }
  __shared__ float ss[8], sq[8];
  if ((tid & 31) == 0) { ss[tid >> 5] = s; sq[tid >> 5] = q; }
  __syncthreads();
  float ts = 0.f, tq = 0.f;
#pragma unroll
  for (int k = 0; k < 8; k++) { ts += ss[k]; tq += sq[k]; }
  float mu = ts * (1.f / WID);
  float var = tq * (1.f / WID) - mu * mu;
  float rstd = rsqrtf(var + 1e-5f);
  float* yr = Y + (size_t)row * WID;
  yr[tid]       = (v0 - mu) * rstd * sc[tid]       + bi[tid];
  yr[tid + 256] = (v1 - mu) * rstd * sc[tid + 256] + bi[tid + 256];
}

// ---------------- tf32 tensor-core GEMM (NT): C[m,n] = sum_k A[m,k]*B[n,k] ----------------
// 128x128 block, 8 warps (2m x 4n), each warp 64x32 via m16n8k8 tf32 MMA.
// EPI: 0 none, 1 +bias, 2 +bias->gelu, 3 +bias+residual
template <int EPI>
__global__ __launch_bounds__(256) void gemm_tc(
    const float* __restrict__ A, const float* __restrict__ Bw,
    const float* __restrict__ bias, const float* __restrict__ Res,
    float* __restrict__ C, int N, int K) {
  // stride 136: frag reads bank-conflict-free (8*(lane%4)+lane/4 spans 0..31)
  __shared__ __align__(16) float As[16][136];
  __shared__ __align__(16) float Bs[16][136];
  const int bm = blockIdx.y * 128;
  const int bn = blockIdx.x * 128;
  const int tid = threadIdx.x;
  const int lane = tid & 31, wid = tid >> 5;
  const int wm = wid & 1, wn = wid >> 1;      // warp tile: rows wm*64, cols wn*32
  const int l4 = lane & 3, l28 = lane >> 2;   // fragment coords
  const int lr = tid >> 2;                    // 0..63 (gmem loader row)
  const int lk = (tid & 3) << 2;              // 0,4,8,12 (gmem loader k)
  const float* Ag = A + (size_t)(bm + lr) * K + lk;
  const float* Bg = Bw + (size_t)(bn + lr) * K + lk;

  float acc[4][4][4];
#pragma unroll
  for (int i = 0; i < 4; i++)
#pragma unroll
    for (int j = 0; j < 4; j++)
#pragma unroll
      for (int r = 0; r < 4; r++) acc[i][j][r] = 0.f;

  for (int k0 = 0; k0 < K; k0 += 16) {
    float4 a0 = *(const float4*)(Ag + k0);
    float4 a1 = *(const float4*)(Ag + (size_t)64 * K + k0);
    float4 b0 = *(const float4*)(Bg + k0);
    float4 b1 = *(const float4*)(Bg + (size_t)64 * K + k0);
    As[lk + 0][lr] = ftf32(a0.x); As[lk + 1][lr] = ftf32(a0.y);
    As[lk + 2][lr] = ftf32(a0.z); As[lk + 3][lr] = ftf32(a0.w);
    As[lk + 0][lr + 64] = ftf32(a1.x); As[lk + 1][lr + 64] = ftf32(a1.y);
    As[lk + 2][lr + 64] = ftf32(a1.z); As[lk + 3][lr + 64] = ftf32(a1.w);
    Bs[lk + 0][lr] = ftf32(b0.x); Bs[lk + 1][lr] = ftf32(b0.y);
    Bs[lk + 2][lr] = ftf32(b0.z); Bs[lk + 3][lr] = ftf32(b0.w);
    Bs[lk + 0][lr + 64] = ftf32(b1.x); Bs[lk + 1][lr + 64] = ftf32(b1.y);
    Bs[lk + 2][lr + 64] = ftf32(b1.z); Bs[lk + 3][lr + 64] = ftf32(b1.w);
    __syncthreads();
#pragma unroll
    for (int ks = 0; ks < 16; ks += 8) {
      float af[4][4], bf[4][2];
#pragma unroll
      for (int mi = 0; mi < 4; mi++) {
        int am = wm * 64 + mi * 16 + l28;
        af[mi][0] = As[ks + l4][am];
        af[mi][1] = As[ks + l4][am + 8];
        af[mi][2] = As[ks + 4 + l4][am];
        af[mi][3] = As[ks + 4 + l4][am + 8];
      }
#pragma unroll
      for (int nj = 0; nj < 4; nj++) {
        int cn = wn * 32 + nj * 8 + l28;
        bf[nj][0] = Bs[ks + l4][cn];
        bf[nj][1] = Bs[ks + 4 + l4][cn];
      }
#pragma unroll
      for (int mi = 0; mi < 4; mi++)
#pragma unroll
        for (int nj = 0; nj < 4; nj++) mma_tf32(acc[mi][nj], af[mi], bf[nj]);
    }
    __syncthreads();
  }

  // epilogue: c0,c1 at (row, col..col+1), c2,c3 at (row+8, col..col+1)
#pragma unroll
  for (int mi = 0; mi < 4; mi++) {
    int row0 = bm + wm * 64 + mi * 16 + l28;
#pragma unroll
    for (int half = 0; half < 2; half++) {
      int row = row0 + half * 8;
      float* crow = C + (size_t)row * N + bn + wn * 32;
      const float* rrow = (EPI == 3) ? (Res + (size_t)row * N + bn + wn * 32) : nullptr;
#pragma unroll
      for (int nj = 0; nj < 4; nj++) {
        int col = nj * 8 + 2 * l4;
        float v0 = acc[mi][nj][half * 2 + 0];
        float v1 = acc[mi][nj][half * 2 + 1];
        if (EPI >= 1) {
          v0 += bias[bn + wn * 32 + col];
          v1 += bias[bn + wn * 32 + col + 1];
        }
        if (EPI == 2) {
          v0 = 0.5f * v0 * (1.f + erff(v0 * 0.70710678118654752f));
          v1 = 0.5f * v1 * (1.f + erff(v1 * 0.70710678118654752f));
        }
        if (EPI == 3) { v0 += rrow[col]; v1 += rrow[col + 1]; }
        *(float2*)(crow + col) = make_float2(v0, v1);
      }
    }
  }
}

// ---------------- structured attention ----------------
__global__ __launch_bounds__(256) void attn_kernel(const float* __restrict__ qkv,
                                                   float* __restrict__ O) {
  const int fi = blockIdx.x >> 1, qt = blockIdx.x & 1;
  const int h = blockIdx.y, b = blockIdx.z;
  const int fs = fi * BLK;
  const int q0 = fs + qt * 64;
  const int nE = (fi > 0) ? (1 + 17 * (fi + 1)) : 17;
  const int nK = 128 + nE;
  const float* base = qkv + (size_t)b * SEQL * 1536;

  __shared__ __align__(16) float Qs[64][68];
  __shared__ __align__(16) float Ks[64][36];
  __shared__ __align__(16) float Vs[32][68];
  __shared__ __align__(16) float Ps[32][68];
  __shared__ float m_s[64], l_s[64], al_s[64];

  const int tid = threadIdx.x;
  {
    int qr = tid >> 2;
    int c4 = tid & 3;
    const float* qrow = base + (size_t)(q0 + qr) * 1536 + h * 64;
#pragma unroll
    for (int j = 0; j < 4; j++) {
      int d = (c4 * 4 + j) * 4;
      float4 v = *(const float4*)(qrow + d);
      Qs[d + 0][qr] = v.x * 0.125f; Qs[d + 1][qr] = v.y * 0.125f;
      Qs[d + 2][qr] = v.z * 0.125f; Qs[d + 3][qr] = v.w * 0.125f;
    }
  }
  if (tid < 64) { m_s[tid] = -1e30f; l_s[tid] = 0.f; }

  const int tx = tid & 15, ty = tid >> 4;
  float Oa[4][4];
#pragma unroll
  for (int i = 0; i < 4; i++)
#pragma unroll
    for (int j = 0; j < 4; j++) Oa[i][j] = 0.f;

  const int nCh = (nK + 31) / 32;
  for (int ch = 0; ch < nCh; ch++) {
    const int kb = ch * 32;
    __syncthreads();
    {
      int kr = tid >> 3;
      int c2 = tid & 7;
      int t = kb + kr;
      int pos;
      if (t >= nK) pos = fs;
      else if (t < 128) pos = fs + t;
      else {
        int e = t - 128;
        if (fi > 0) {
          if (e == 0) pos = fs - 1;
          else { int e2 = e - 1; pos = (e2 / 17) * BLK + 128 + (e2 % 17); }
        } else pos = 128 + e;
      }
      const float* krow = base + (size_t)pos * 1536 + 512 + h * 64;
      const float* vrow = base + (size_t)pos * 1536 + 1024 + h * 64;
#pragma unroll
      for (int j = 0; j < 2; j++) {
        int d = (c2 * 2 + j) * 4;
        float4 kv = *(const float4*)(krow + d);
        Ks[d + 0][kr] = kv.x; Ks[d + 1][kr] = kv.y; Ks[d + 2][kr] = kv.z; Ks[d + 3][kr] = kv.w;
        float4 vv = *(const float4*)(vrow + d);
        *(float4*)(&Vs[kr][d]) = vv;
      }
    }
    __syncthreads();
    float sreg[4][2];
#pragma unroll
    for (int i = 0; i < 4; i++) { sreg[i][0] = 0.f; sreg[i][1] = 0.f; }
#pragma unroll
    for (int d = 0; d < 64; d++) {
      float qv[4];
      *(float4*)qv = *(const float4*)(&Qs[d][ty * 4]);
      float k0 = Ks[d][tx * 2], k1 = Ks[d][tx * 2 + 1];
#pragma unroll
      for (int i = 0; i < 4; i++) {
        sreg[i][0] = fmaf(qv[i], k0, sreg[i][0]);
        sreg[i][1] = fmaf(qv[i], k1, sreg[i][1]);
      }
    }
#pragma unroll
    for (int j = 0; j < 2; j++) {
      int t = kb + tx * 2 + j;
      bool valid = (t < nK);
#pragma unroll
      for (int i = 0; i < 4; i++)
        Ps[tx * 2 + j][ty * 4 + i] = valid ? sreg[i][j] : -1e30f;
    }
    __syncthreads();
    if (tid < 64) {
      float mo = m_s[tid];
      float mc = -1e30f;
#pragma unroll
      for (int kk = 0; kk < 32; kk++) mc = fmaxf(mc, Ps[kk][tid]);
      float mn = fmaxf(mo, mc);
      float al = expf(mo - mn);
      float ls = 0.f;
#pragma unroll
      for (int kk = 0; kk < 32; kk++) {
        float p = expf(Ps[kk][tid] - mn);
        Ps[kk][tid] = p;
        ls += p;
      }
      m_s[tid] = mn;
      l_s[tid] = l_s[tid] * al + ls;
      al_s[tid] = al;
    }
    __syncthreads();
#pragma unroll
    for (int i = 0; i < 4; i++) {
      float al = al_s[ty * 4 + i];
#pragma unroll
      for (int j = 0; j < 4; j++) Oa[i][j] *= al;
    }
#pragma unroll
    for (int kk = 0; kk < 32; kk++) {
      float pr[4], vr[4];
      *(float4*)pr = *(const float4*)(&Ps[kk][ty * 4]);
      *(float4*)vr = *(const float4*)(&Vs[kk][tx * 4]);
#pragma unroll
      for (int i = 0; i < 4; i++)
#pragma unroll
        for (int j = 0; j < 4; j++) Oa[i][j] = fmaf(pr[i], vr[j], Oa[i][j]);
    }
  }
#pragma unroll
  for (int i = 0; i < 4; i++) {
    int q = ty * 4 + i;
    float inv = 1.f / l_s[q];
    float* orow = O + (size_t)(b * SEQL + q0 + q) * WID + h * 64 + tx * 4;
    float4 ov = make_float4(Oa[i][0] * inv, Oa[i][1] * inv, Oa[i][2] * inv, Oa[i][3] * inv);
    *(float4*)orow = ov;
  }
}

// ---------------- non-frame rows: attention output == V ----------------
__global__ void copyv_kernel() {
  int idx = blockIdx.x * 256 + threadIdx.x;
  if (idx >= NB * NFR * 18 * WID) return;
  int c = idx & 511;
  int rid = idx >> 9;
  int b = rid / (NFR * 18);
  int rr = rid % (NFR * 18);
  int fi = rr / 18, r = 128 + rr % 18;
  size_t srow = (size_t)b * SEQL + fi * BLK + r;
  g_o[srow * WID + c] = g_qkv[srow * 1536 + 1024 + c];
}

// ---------------- gather frame-token rows for the prediction head ----------------
__global__ void gather_kernel() {
  int idx = blockIdx.x * 256 + threadIdx.x;
  if (idx >= MHEAD * WID) return;
  int c = idx & 511, rid = idx >> 9;
  int b = rid / 1536, m = rid % 1536;
  int s = (m >> 7) * BLK + (m & 127);
  g_hf[(size_t)rid * WID + c] = g_h[(size_t)(b * SEQL + s) * WID + c];
}

// ---------------- launch ----------------
extern "C" void kernel_launch(void* const* d_in, const int* in_sizes, int n_in,
                              void* d_out, int out_size) {
  const float* x     = (const float*)d_in[0];
  const float* f     = (const float*)d_in[1];
  const float* delim = (const float*)d_in[2];
  const float* ln1s  = (const float*)d_in[3];
  const float* ln1b  = (const float*)d_in[4];
  const float* wqkv  = (const float*)d_in[5];
  const float* bqkv  = (const float*)d_in[6];
  const float* wout  = (const float*)d_in[7];
  const float* bout  = (const float*)d_in[8];
  const float* ln2s  = (const float*)d_in[9];
  const float* ln2b  = (const float*)d_in[10];
  const float* wfc   = (const float*)d_in[11];
  const float* bfc   = (const float*)d_in[12];
  const float* wproj = (const float*)d_in[13];
  const float* bproj = (const float*)d_in[14];
  const float* whead = (const float*)d_in[15];
  float* out = (float*)d_out;

  float *h, *a, *qkv, *o, *mlp, *hf;
  cudaGetSymbolAddress((void**)&h, g_h);
  cudaGetSymbolAddress((void**)&a, g_a);
  cudaGetSymbolAddress((void**)&qkv, g_qkv);
  cudaGetSymbolAddress((void**)&o, g_o);
  cudaGetSymbolAddress((void**)&mlp, g_mlp);
  cudaGetSymbolAddress((void**)&hf, g_hf);

  build_h_kernel<<<MPAD, 256>>>(x, f, delim);

  for (int l = 0; l < NLAYER; l++) {
    ln_kernel<<<MROWS, 256>>>(h, ln1s + l * WID, ln1b + l * WID, a);
    gemm_tc<1><<<dim3(1536 / 128, MPAD / 128), 256>>>(
        a, wqkv + (size_t)l * 1536 * WID, bqkv + l * 1536, nullptr, qkv, 1536, WID);
    attn_kernel<<<dim3(NFR * 2, NH, NB), 256>>>(qkv, o);
    copyv_kernel<<<(NB * NFR * 18 * WID + 255) / 256, 256>>>();
    gemm_tc<3><<<dim3(WID / 128, MPAD / 128), 256>>>(
        o, wout + (size_t)l * WID * WID, bout + l * WID, h, h, WID, WID);
    ln_kernel<<<MROWS, 256>>>(h, ln2s + l * WID, ln2b + l * WID, a);
    gemm_tc<2><<<dim3(2048 / 128, MPAD / 128), 256>>>(
        a, wfc + (size_t)l * 2048 * WID, bfc + l * 2048, nullptr, mlp, 2048, WID);
    gemm_tc<3><<<dim3(WID / 128, MPAD / 128), 256>>>(
        mlp, wproj + (size_t)l * WID * 2048, bproj + l * WID, h, h, WID, 2048);
  }

  gather_kernel<<<(MHEAD * WID + 255) / 256, 256>>>();
  gemm_tc<0><<<dim3(1024 / 128, MHEAD / 128), 256>>>(
      hf, whead, nullptr, nullptr, out, 1024, WID);
}

// round 8
// speedup vs baseline: 2.1832x; 1.1970x over previous
#include <cuda_runtime.h>
#include <stdint.h>
#include <math.h>

// ---------------- problem constants ----------------
constexpr int WID    = 512;
constexpr int SEQL   = 1752;
constexpr int BLK    = 146;   // 128 frame + delim + 16 dyn + delim
constexpr int NFR    = 12;    // N frames (13-1)
constexpr int NB     = 4;     // batch
constexpr int NH     = 8;     // heads
constexpr int NLAYER = 6;
constexpr int MROWS  = NB * SEQL;        // 7008
constexpr int MPAD   = 7040;             // padded to /128
constexpr int MHEAD  = NB * NFR * 128;   // 6144 logit rows

// ---------------- scratch (device globals; no cudaMalloc allowed) ----------------
__device__ float g_h  [(size_t)MPAD * WID];
__device__ float g_a  [(size_t)MPAD * WID];
__device__ float g_qkv[(size_t)MPAD * 3 * WID];
__device__ float g_o  [(size_t)MPAD * WID];
__device__ float g_mlp[(size_t)MPAD * 4 * WID];
__device__ float g_hf [(size_t)MHEAD * WID];

// ---------------- helpers ----------------
__device__ __forceinline__ float ftf32(float x) {
  unsigned int u = __float_as_uint(x), r;
  asm("cvt.rna.tf32.f32 %0, %1;" : "=r"(r) : "r"(u));
  return __uint_as_float(r);
}

__device__ __forceinline__ void mma_tf32(float* d, const float* a, const float* b) {
  asm volatile(
      "mma.sync.aligned.m16n8k8.row.col.f32.tf32.tf32.f32 "
      "{%0,%1,%2,%3}, {%4,%5,%6,%7}, {%8,%9}, {%0,%1,%2,%3};"
      : "+f"(d[0]), "+f"(d[1]), "+f"(d[2]), "+f"(d[3])
      : "r"(__float_as_uint(a[0])), "r"(__float_as_uint(a[1])),
        "r"(__float_as_uint(a[2])), "r"(__float_as_uint(a[3])),
        "r"(__float_as_uint(b[0])), "r"(__float_as_uint(b[1])));
}

__device__ __forceinline__ void cp_async16(void* smem_dst, const void* gsrc) {
  unsigned int sa = (unsigned int)__cvta_generic_to_shared(smem_dst);
  asm volatile("cp.async.ca.shared.global [%0], [%1], 16;" :: "r"(sa), "l"(gsrc));
}

// ---------------- build h = concat(x, delim, f, delim) + pos_emb ----------------
__global__ void build_h_kernel(const float* __restrict__ x, const float* __restrict__ f,
                               const float* __restrict__ delim) {
  __shared__ float rden[256];
  int tid = threadIdx.x;  // 256 threads
  rden[tid] = (float)(1.0 / pow(10000.0, (double)tid / 256.0));
  __syncthreads();
  int row = blockIdx.x;
  float* hr = g_h + (size_t)row * WID;
  if (row >= MROWS) { hr[tid] = 0.f; hr[tid + 256] = 0.f; return; }
  int b = row / SEQL, s = row % SEQL;
  int fi = s / BLK, r = s - fi * BLK;
  const float* src;
  if (r < 128)                    src = x + (size_t)((b * NFR + fi) * 128 + r) * WID;
  else if (r == 128 || r == 145)  src = delim;
  else                            src = f + (size_t)(b * NFR * 16 + fi * 16 + (r - 129)) * WID;
#pragma unroll
  for (int c = tid; c < WID; c += 256) {
    float ang = (float)s * rden[c >> 1];
    float p = (c & 1) ? cosf(ang) : sinf(ang);
    hr[c] = src[c] + p;
  }
}

// ---------------- LayerNorm: one block per row ----------------
__global__ void ln_kernel(const float* __restrict__ X, const float* __restrict__ sc,
                          const float* __restrict__ bi, float* __restrict__ Y) {
  int row = blockIdx.x;
  const float* xr = X + (size_t)row * WID;
  int tid = threadIdx.x;  // 256
  float v0 = xr[tid], v1 = xr[tid + 256];
  float s = v0 + v1, q = v0 * v0 + v1 * v1;
#pragma unroll
  for (int o = 16; o; o >>= 1) {
    s += __shfl_xor_sync(0xffffffffu, s, o);
    q += __shfl_xor_sync(0xffffffffu, q, o);
  }
  __shared__ float ss[8], sq[8];
  if ((tid & 31) == 0) { ss[tid >> 5] = s; sq[tid >> 5] = q; }
  __syncthreads();
  float ts = 0.f, tq = 0.f;
#pragma unroll
  for (int k = 0; k < 8; k++) { ts += ss[k]; tq += sq[k]; }
  float mu = ts * (1.f / WID);
  float var = tq * (1.f / WID) - mu * mu;
  float rstd = rsqrtf(var + 1e-5f);
  float* yr = Y + (size_t)row * WID;
  yr[tid]       = (v0 - mu) * rstd * sc[tid]       + bi[tid];
  yr[tid + 256] = (v1 - mu) * rstd * sc[tid + 256] + bi[tid + 256];
}

// ---------------- tf32 tensor-core GEMM (NT): C[m,n] = sum_k A[m,k]*B[n,k] ----------------
// 128x128 block, 8 warps (2m x 4n), each warp 64x32 via m16n8k8 tf32 MMA.
// 2-stage cp.async pipeline; smem [m][k] with row stride 20 (conflict-free frags).
// EPI: 0 none, 1 +bias, 2 +bias->gelu, 3 +bias+residual
template <int EPI>
__global__ __launch_bounds__(256, 2) void gemm_tc(
    const float* __restrict__ A, const float* __restrict__ Bw,
    const float* __restrict__ bias, const float* __restrict__ Res,
    float* __restrict__ C, int N, int K) {
  __shared__ __align__(16) float As[2][128][20];
  __shared__ __align__(16) float Bs[2][128][20];
  const int bm = blockIdx.y * 128;
  const int bn = blockIdx.x * 128;
  const int tid = threadIdx.x;
  const int lane = tid & 31, wid = tid >> 5;
  const int wm = wid & 1, wn = wid >> 1;      // warp tile: rows wm*64, cols wn*32
  const int l4 = lane & 3, l28 = lane >> 2;   // fragment coords
  const int r0 = tid >> 2;                    // loader row 0..63
  const int seg = (tid & 3) << 2;             // loader k-offset: 0,4,8,12
  const float* Ag = A + (size_t)(bm + r0) * K + seg;
  const float* Bg = Bw + (size_t)(bn + r0) * K + seg;

  float acc[4][4][4];
#pragma unroll
  for (int i = 0; i < 4; i++)
#pragma unroll
    for (int j = 0; j < 4; j++)
#pragma unroll
      for (int r = 0; r < 4; r++) acc[i][j][r] = 0.f;

  const int nT = K >> 4;  // 16-wide K tiles

  // prologue: stage 0
  cp_async16(&As[0][r0][seg],      Ag);
  cp_async16(&As[0][r0 + 64][seg], Ag + (size_t)64 * K);
  cp_async16(&Bs[0][r0][seg],      Bg);
  cp_async16(&Bs[0][r0 + 64][seg], Bg + (size_t)64 * K);
  asm volatile("cp.async.commit_group;");

  for (int it = 0; it < nT; it++) {
    asm volatile("cp.async.wait_group 0;");
    __syncthreads();
    // prefetch next stage (overlaps with compute below). Safe: all threads have
    // finished reading buffer (it+1)&1 (their compute of iter it-1 precedes this sync).
    if (it + 1 < nT) {
      const int ns = (it + 1) & 1;
      const int ko = (it + 1) << 4;
      cp_async16(&As[ns][r0][seg],      Ag + ko);
      cp_async16(&As[ns][r0 + 64][seg], Ag + (size_t)64 * K + ko);
      cp_async16(&Bs[ns][r0][seg],      Bg + ko);
      cp_async16(&Bs[ns][r0 + 64][seg], Bg + (size_t)64 * K + ko);
      asm volatile("cp.async.commit_group;");
    }
    const float (*Asb)[20] = As[it & 1];
    const float (*Bsb)[20] = Bs[it & 1];
#pragma unroll
    for (int ks = 0; ks < 16; ks += 8) {
      float af[4][4], bf[4][2];
#pragma unroll
      for (int mi = 0; mi < 4; mi++) {
        int am = wm * 64 + mi * 16 + l28;
        af[mi][0] = ftf32(Asb[am][ks + l4]);
        af[mi][1] = ftf32(Asb[am + 8][ks + l4]);
        af[mi][2] = ftf32(Asb[am][ks + 4 + l4]);
        af[mi][3] = ftf32(Asb[am + 8][ks + 4 + l4]);
      }
#pragma unroll
      for (int nj = 0; nj < 4; nj++) {
        int cn = wn * 32 + nj * 8 + l28;
        bf[nj][0] = ftf32(Bsb[cn][ks + l4]);
        bf[nj][1] = ftf32(Bsb[cn][ks + 4 + l4]);
      }
#pragma unroll
      for (int mi = 0; mi < 4; mi++)
#pragma unroll
        for (int nj = 0; nj < 4; nj++) mma_tf32(acc[mi][nj], af[mi], bf[nj]);
    }
  }

  // epilogue: c0,c1 at (row, col..col+1), c2,c3 at (row+8, col..col+1)
#pragma unroll
  for (int mi = 0; mi < 4; mi++) {
    int row0 = bm + wm * 64 + mi * 16 + l28;
#pragma unroll
    for (int half = 0; half < 2; half++) {
      int row = row0 + half * 8;
      float* crow = C + (size_t)row * N + bn + wn * 32;
      const float* rrow = (EPI == 3) ? (Res + (size_t)row * N + bn + wn * 32) : nullptr;
#pragma unroll
      for (int nj = 0; nj < 4; nj++) {
        int col = nj * 8 + 2 * l4;
        float v0 = acc[mi][nj][half * 2 + 0];
        float v1 = acc[mi][nj][half * 2 + 1];
        if (EPI >= 1) {
          v0 += bias[bn + wn * 32 + col];
          v1 += bias[bn + wn * 32 + col + 1];
        }
        if (EPI == 2) {
          v0 = 0.5f * v0 * (1.f + erff(v0 * 0.70710678118654752f));
          v1 = 0.5f * v1 * (1.f + erff(v1 * 0.70710678118654752f));
        }
        if (EPI == 3) { v0 += rrow[col]; v1 += rrow[col + 1]; }
        *(float2*)(crow + col) = make_float2(v0, v1);
      }
    }
  }
}

// ---------------- structured attention ----------------
__global__ __launch_bounds__(256) void attn_kernel(const float* __restrict__ qkv,
                                                   float* __restrict__ O) {
  const int fi = blockIdx.x >> 1, qt = blockIdx.x & 1;
  const int h = blockIdx.y, b = blockIdx.z;
  const int fs = fi * BLK;
  const int q0 = fs + qt * 64;
  const int nE = (fi > 0) ? (1 + 17 * (fi + 1)) : 17;
  const int nK = 128 + nE;
  const float* base = qkv + (size_t)b * SEQL * 1536;

  __shared__ __align__(16) float Qs[64][68];
  __shared__ __align__(16) float Ks[64][36];
  __shared__ __align__(16) float Vs[32][68];
  __shared__ __align__(16) float Ps[32][68];
  __shared__ float m_s[64], l_s[64], al_s[64];

  const int tid = threadIdx.x;
  {
    int qr = tid >> 2;
    int c4 = tid & 3;
    const float* qrow = base + (size_t)(q0 + qr) * 1536 + h * 64;
#pragma unroll
    for (int j = 0; j < 4; j++) {
      int d = (c4 * 4 + j) * 4;
      float4 v = *(const float4*)(qrow + d);
      Qs[d + 0][qr] = v.x * 0.125f; Qs[d + 1][qr] = v.y * 0.125f;
      Qs[d + 2][qr] = v.z * 0.125f; Qs[d + 3][qr] = v.w * 0.125f;
    }
  }
  if (tid < 64) { m_s[tid] = -1e30f; l_s[tid] = 0.f; }

  const int tx = tid & 15, ty = tid >> 4;
  float Oa[4][4];
#pragma unroll
  for (int i = 0; i < 4; i++)
#pragma unroll
    for (int j = 0; j < 4; j++) Oa[i][j] = 0.f;

  const int nCh = (nK + 31) / 32;
  for (int ch = 0; ch < nCh; ch++) {
    const int kb = ch * 32;
    __syncthreads();
    {
      int kr = tid >> 3;
      int c2 = tid & 7;
      int t = kb + kr;
      int pos;
      if (t >= nK) pos = fs;
      else if (t < 128) pos = fs + t;
      else {
        int e = t - 128;
        if (fi > 0) {
          if (e == 0) pos = fs - 1;
          else { int e2 = e - 1; pos = (e2 / 17) * BLK + 128 + (e2 % 17); }
        } else pos = 128 + e;
      }
      const float* krow = base + (size_t)pos * 1536 + 512 + h * 64;
      const float* vrow = base + (size_t)pos * 1536 + 1024 + h * 64;
#pragma unroll
      for (int j = 0; j < 2; j++) {
        int d = (c2 * 2 + j) * 4;
        float4 kv = *(const float4*)(krow + d);
        Ks[d + 0][kr] = kv.x; Ks[d + 1][kr] = kv.y; Ks[d + 2][kr] = kv.z; Ks[d + 3][kr] = kv.w;
        float4 vv = *(const float4*)(vrow + d);
        *(float4*)(&Vs[kr][d]) = vv;
      }
    }
    __syncthreads();
    float sreg[4][2];
#pragma unroll
    for (int i = 0; i < 4; i++) { sreg[i][0] = 0.f; sreg[i][1] = 0.f; }
#pragma unroll
    for (int d = 0; d < 64; d++) {
      float qv[4];
      *(float4*)qv = *(const float4*)(&Qs[d][ty * 4]);
      float k0 = Ks[d][tx * 2], k1 = Ks[d][tx * 2 + 1];
#pragma unroll
      for (int i = 0; i < 4; i++) {
        sreg[i][0] = fmaf(qv[i], k0, sreg[i][0]);
        sreg[i][1] = fmaf(qv[i], k1, sreg[i][1]);
      }
    }
#pragma unroll
    for (int j = 0; j < 2; j++) {
      int t = kb + tx * 2 + j;
      bool valid = (t < nK);
#pragma unroll
      for (int i = 0; i < 4; i++)
        Ps[tx * 2 + j][ty * 4 + i] = valid ? sreg[i][j] : -1e30f;
    }
    __syncthreads();
    if (tid < 64) {
      float mo = m_s[tid];
      float mc = -1e30f;
#pragma unroll
      for (int kk = 0; kk < 32; kk++) mc = fmaxf(mc, Ps[kk][tid]);
      float mn = fmaxf(mo, mc);
      float al = expf(mo - mn);
      float ls = 0.f;
#pragma unroll
      for (int kk = 0; kk < 32; kk++) {
        float p = expf(Ps[kk][tid] - mn);
        Ps[kk][tid] = p;
        ls += p;
      }
      m_s[tid] = mn;
      l_s[tid] = l_s[tid] * al + ls;
      al_s[tid] = al;
    }
    __syncthreads();
#pragma unroll
    for (int i = 0; i < 4; i++) {
      float al = al_s[ty * 4 + i];
#pragma unroll
      for (int j = 0; j < 4; j++) Oa[i][j] *= al;
    }
#pragma unroll
    for (int kk = 0; kk < 32; kk++) {
      float pr[4], vr[4];
      *(float4*)pr = *(const float4*)(&Ps[kk][ty * 4]);
      *(float4*)vr = *(const float4*)(&Vs[kk][tx * 4]);
#pragma unroll
      for (int i = 0; i < 4; i++)
#pragma unroll
        for (int j = 0; j < 4; j++) Oa[i][j] = fmaf(pr[i], vr[j], Oa[i][j]);
    }
  }
#pragma unroll
  for (int i = 0; i < 4; i++) {
    int q = ty * 4 + i;
    float inv = 1.f / l_s[q];
    float* orow = O + (size_t)(b * SEQL + q0 + q) * WID + h * 64 + tx * 4;
    float4 ov = make_float4(Oa[i][0] * inv, Oa[i][1] * inv, Oa[i][2] * inv, Oa[i][3] * inv);
    *(float4*)orow = ov;
  }
}

// ---------------- non-frame rows: attention output == V ----------------
__global__ void copyv_kernel() {
  int idx = blockIdx.x * 256 + threadIdx.x;
  if (idx >= NB * NFR * 18 * WID) return;
  int c = idx & 511;
  int rid = idx >> 9;
  int b = rid / (NFR * 18);
  int rr = rid % (NFR * 18);
  int fi = rr / 18, r = 128 + rr % 18;
  size_t srow = (size_t)b * SEQL + fi * BLK + r;
  g_o[srow * WID + c] = g_qkv[srow * 1536 + 1024 + c];
}

// ---------------- gather frame-token rows for the prediction head ----------------
__global__ void gather_kernel() {
  int idx = blockIdx.x * 256 + threadIdx.x;
  if (idx >= MHEAD * WID) return;
  int c = idx & 511, rid = idx >> 9;
  int b = rid / 1536, m = rid % 1536;
  int s = (m >> 7) * BLK + (m & 127);
  g_hf[(size_t)rid * WID + c] = g_h[(size_t)(b * SEQL + s) * WID + c];
}

// ---------------- launch ----------------
extern "C" void kernel_launch(void* const* d_in, const int* in_sizes, int n_in,
                              void* d_out, int out_size) {
  const float* x     = (const float*)d_in[0];
  const float* f     = (const float*)d_in[1];
  const float* delim = (const float*)d_in[2];
  const float* ln1s  = (const float*)d_in[3];
  const float* ln1b  = (const float*)d_in[4];
  const float* wqkv  = (const float*)d_in[5];
  const float* bqkv  = (const float*)d_in[6];
  const float* wout  = (const float*)d_in[7];
  const float* bout  = (const float*)d_in[8];
  const float* ln2s  = (const float*)d_in[9];
  const float* ln2b  = (const float*)d_in[10];
  const float* wfc   = (const float*)d_in[11];
  const float* bfc   = (const float*)d_in[12];
  const float* wproj = (const float*)d_in[13];
  const float* bproj = (const float*)d_in[14];
  const float* whead = (const float*)d_in[15];
  float* out = (float*)d_out;

  float *h, *a, *qkv, *o, *mlp, *hf;
  cudaGetSymbolAddress((void**)&h, g_h);
  cudaGetSymbolAddress((void**)&a, g_a);
  cudaGetSymbolAddress((void**)&qkv, g_qkv);
  cudaGetSymbolAddress((void**)&o, g_o);
  cudaGetSymbolAddress((void**)&mlp, g_mlp);
  cudaGetSymbolAddress((void**)&hf, g_hf);

  build_h_kernel<<<MPAD, 256>>>(x, f, delim);

  for (int l = 0; l < NLAYER; l++) {
    ln_kernel<<<MROWS, 256>>>(h, ln1s + l * WID, ln1b + l * WID, a);
    gemm_tc<1><<<dim3(1536 / 128, MPAD / 128), 256>>>(
        a, wqkv + (size_t)l * 1536 * WID, bqkv + l * 1536, nullptr, qkv, 1536, WID);
    attn_kernel<<<dim3(NFR * 2, NH, NB), 256>>>(qkv, o);
    copyv_kernel<<<(NB * NFR * 18 * WID + 255) / 256, 256>>>();
    gemm_tc<3><<<dim3(WID / 128, MPAD / 128), 256>>>(
        o, wout + (size_t)l * WID * WID, bout + l * WID, h, h, WID, WID);
    ln_kernel<<<MROWS, 256>>>(h, ln2s + l * WID, ln2b + l * WID, a);
    gemm_tc<2><<<dim3(2048 / 128, MPAD / 128), 256>>>(
        a, wfc + (size_t)l * 2048 * WID, bfc + l * 2048, nullptr, mlp, 2048, WID);
    gemm_tc<3><<<dim3(WID / 128, MPAD / 128), 256>>>(
        mlp, wproj + (size_t)l * WID * 2048, bproj + l * WID, h, h, WID, 2048);
  }

  gather_kernel<<<(MHEAD * WID + 255) / 256, 256>>>();
  gemm_tc<0><<<dim3(1024 / 128, MHEAD / 128), 256>>>(
      hf, whead, nullptr, nullptr, out, 1024, WID);
}

// round 9
// speedup vs baseline: 2.2018x; 1.0085x over previous
#include <cuda_runtime.h>
#include <stdint.h>
#include <math.h>

// ---------------- problem constants ----------------
constexpr int WID    = 512;
constexpr int SEQL   = 1752;
constexpr int BLK    = 146;   // 128 frame + delim + 16 dyn + delim
constexpr int NFR    = 12;    // N frames (13-1)
constexpr int NB     = 4;     // batch
constexpr int NH     = 8;     // heads
constexpr int NLAYER = 6;
constexpr int MROWS  = NB * SEQL;        // 7008
constexpr int MPAD   = 7040;             // padded to /128
constexpr int MHEAD  = NB * NFR * 128;   // 6144 logit rows

// ---------------- scratch (device globals; no cudaMalloc allowed) ----------------
__device__ float g_h  [(size_t)MPAD * WID];
__device__ float g_a  [(size_t)MPAD * WID];
__device__ float g_qkv[(size_t)MPAD * 3 * WID];
__device__ float g_o  [(size_t)MPAD * WID];
__device__ float g_mlp[(size_t)MPAD * 4 * WID];
__device__ float g_hf [(size_t)MHEAD * WID];
// tf32-pre-rounded weights: qkv | out | fc | proj | head
constexpr size_t W_QKV  = 0;
constexpr size_t W_OUT  = W_QKV + (size_t)NLAYER * 1536 * 512;   // 4718592
constexpr size_t W_FC   = W_OUT + (size_t)NLAYER * 512 * 512;    // 6291456
constexpr size_t W_PROJ = W_FC  + (size_t)NLAYER * 2048 * 512;   // 12582912
constexpr size_t W_HEAD = W_PROJ + (size_t)NLAYER * 512 * 2048;  // 18874368
constexpr size_t W_TOT  = W_HEAD + (size_t)1024 * 512;           // 19398656
__device__ float g_w[W_TOT];

// ---------------- helpers ----------------
__device__ __forceinline__ float ftf32(float x) {
  unsigned int u = __float_as_uint(x), r;
  asm("cvt.rna.tf32.f32 %0, %1;" : "=r"(r) : "r"(u));
  return __uint_as_float(r);
}

__device__ __forceinline__ void mma_tf32(float* d, const float* a, const float* b) {
  asm volatile(
      "mma.sync.aligned.m16n8k8.row.col.f32.tf32.tf32.f32 "
      "{%0,%1,%2,%3}, {%4,%5,%6,%7}, {%8,%9}, {%0,%1,%2,%3};"
      : "+f"(d[0]), "+f"(d[1]), "+f"(d[2]), "+f"(d[3])
      : "r"(__float_as_uint(a[0])), "r"(__float_as_uint(a[1])),
        "r"(__float_as_uint(a[2])), "r"(__float_as_uint(a[3])),
        "r"(__float_as_uint(b[0])), "r"(__float_as_uint(b[1])));
}

__device__ __forceinline__ void cp_async16(void* smem_dst, const void* gsrc) {
  unsigned int sa = (unsigned int)__cvta_generic_to_shared(smem_dst);
  asm volatile("cp.async.ca.shared.global [%0], [%1], 16;" :: "r"(sa), "l"(gsrc));
}

// ---------------- weight pre-rounding (rna -> tf32 bits, stored as fp32) ----------------
__global__ void round_w_kernel(const float* __restrict__ src, float* __restrict__ dst, int n4) {
  int i = blockIdx.x * 256 + threadIdx.x;
  if (i >= n4) return;
  float4 v = ((const float4*)src)[i];
  v.x = ftf32(v.x); v.y = ftf32(v.y); v.z = ftf32(v.z); v.w = ftf32(v.w);
  ((float4*)dst)[i] = v;
}

// ---------------- build h = concat(x, delim, f, delim) + pos_emb ----------------
__global__ void build_h_kernel(const float* __restrict__ x, const float* __restrict__ f,
                               const float* __restrict__ delim) {
  __shared__ float rden[256];
  int tid = threadIdx.x;  // 256 threads
  rden[tid] = (float)(1.0 / pow(10000.0, (double)tid / 256.0));
  __syncthreads();
  int row = blockIdx.x;
  float* hr = g_h + (size_t)row * WID;
  if (row >= MROWS) { hr[tid] = 0.f; hr[tid + 256] = 0.f; return; }
  int b = row / SEQL, s = row % SEQL;
  int fi = s / BLK, r = s - fi * BLK;
  const float* src;
  if (r < 128)                    src = x + (size_t)((b * NFR + fi) * 128 + r) * WID;
  else if (r == 128 || r == 145)  src = delim;
  else                            src = f + (size_t)(b * NFR * 16 + fi * 16 + (r - 129)) * WID;
#pragma unroll
  for (int c = tid; c < WID; c += 256) {
    float ang = (float)s * rden[c >> 1];
    float p = (c & 1) ? cosf(ang) : sinf(ang);
    hr[c] = src[c] + p;
  }
}

// ---------------- LayerNorm: one block per row; output pre-rounded to tf32 ----------------
__global__ void ln_kernel(const float* __restrict__ X, const float* __restrict__ sc,
                          const float* __restrict__ bi, float* __restrict__ Y) {
  int row = blockIdx.x;
  const float* xr = X + (size_t)row * WID;
  int tid = threadIdx.x;  // 256
  float v0 = xr[tid], v1 = xr[tid + 256];
  float s = v0 + v1, q = v0 * v0 + v1 * v1;
#pragma unroll
  for (int o = 16; o; o >>= 1) {
    s += __shfl_xor_sync(0xffffffffu, s, o);
    q += __shfl_xor_sync(0xffffffffu, q, o);
  }
  __shared__ float ss[8], sq[8];
  if ((tid & 31) == 0) { ss[tid >> 5] = s; sq[tid >> 5] = q; }
  __syncthreads();
  float ts = 0.f, tq = 0.f;
#pragma unroll
  for (int k = 0; k < 8; k++) { ts += ss[k]; tq += sq[k]; }
  float mu = ts * (1.f / WID);
  float var = tq * (1.f / WID) - mu * mu;
  float rstd = rsqrtf(var + 1e-5f);
  float* yr = Y + (size_t)row * WID;
  yr[tid]       = ftf32((v0 - mu) * rstd * sc[tid]       + bi[tid]);
  yr[tid + 256] = ftf32((v1 - mu) * rstd * sc[tid + 256] + bi[tid + 256]);
}

// ---------------- tf32 tensor-core GEMM (NT): C[m,n] = sum_k A[m,k]*B[n,k] ----------------
// Inputs must already be tf32-rounded. 128x128 block, 8 warps (2m x 4n), warp 64x32.
// 3-stage cp.async pipeline; smem [m][k] stride 20 (conflict-free frags).
// EPI: 0 none, 1 +bias, 2 +bias->gelu(round), 3 +bias+residual
template <int EPI>
__global__ __launch_bounds__(256, 2) void gemm_tc(
    const float* __restrict__ A, const float* __restrict__ Bw,
    const float* __restrict__ bias, const float* __restrict__ Res,
    float* __restrict__ C, int N, int K) {
  __shared__ __align__(16) float As[3][128][20];
  __shared__ __align__(16) float Bs[3][128][20];
  const int bm = blockIdx.y * 128;
  const int bn = blockIdx.x * 128;
  const int tid = threadIdx.x;
  const int lane = tid & 31, wid = tid >> 5;
  const int wm = wid & 1, wn = wid >> 1;      // warp tile: rows wm*64, cols wn*32
  const int l4 = lane & 3, l28 = lane >> 2;   // fragment coords
  const int r0 = tid >> 2;                    // loader row 0..63
  const int seg = (tid & 3) << 2;             // loader k-offset: 0,4,8,12
  const float* Ag = A + (size_t)(bm + r0) * K + seg;
  const float* Bg = Bw + (size_t)(bn + r0) * K + seg;

  float acc[4][4][4];
#pragma unroll
  for (int i = 0; i < 4; i++)
#pragma unroll
    for (int j = 0; j < 4; j++)
#pragma unroll
      for (int r = 0; r < 4; r++) acc[i][j][r] = 0.f;

  const int nT = K >> 4;  // 16-wide K tiles (>=32 for all our shapes)

  auto issue = [&](int s) {
    const int buf = s % 3;
    const int ko = s << 4;
    cp_async16(&As[buf][r0][seg],      Ag + ko);
    cp_async16(&As[buf][r0 + 64][seg], Ag + (size_t)64 * K + ko);
    cp_async16(&Bs[buf][r0][seg],      Bg + ko);
    cp_async16(&Bs[buf][r0 + 64][seg], Bg + (size_t)64 * K + ko);
    asm volatile("cp.async.commit_group;");
  };

  issue(0);
  issue(1);

  for (int it = 0; it < nT; it++) {
    asm volatile("cp.async.wait_group 1;");  // stage it resident
    __syncthreads();
    // prefetch stage it+2 into buffer (it+2)%3 == (it-1)%3 (freed: all threads
    // passed the sync only after finishing compute(it-1)).
    if (it + 2 < nT) issue(it + 2);
    const float (*Asb)[20] = As[it % 3];
    const float (*Bsb)[20] = Bs[it % 3];
#pragma unroll
    for (int ks = 0; ks < 16; ks += 8) {
      float af[4][4], bf[4][2];
#pragma unroll
      for (int mi = 0; mi < 4; mi++) {
        int am = wm * 64 + mi * 16 + l28;
        af[mi][0] = Asb[am][ks + l4];
        af[mi][1] = Asb[am + 8][ks + l4];
        af[mi][2] = Asb[am][ks + 4 + l4];
        af[mi][3] = Asb[am + 8][ks + 4 + l4];
      }
#pragma unroll
      for (int nj = 0; nj < 4; nj++) {
        int cn = wn * 32 + nj * 8 + l28;
        bf[nj][0] = Bsb[cn][ks + l4];
        bf[nj][1] = Bsb[cn][ks + 4 + l4];
      }
#pragma unroll
      for (int mi = 0; mi < 4; mi++)
#pragma unroll
        for (int nj = 0; nj < 4; nj++) mma_tf32(acc[mi][nj], af[mi], bf[nj]);
    }
  }

  // epilogue: c0,c1 at (row, col..col+1), c2,c3 at (row+8, col..col+1)
#pragma unroll
  for (int mi = 0; mi < 4; mi++) {
    int row0 = bm + wm * 64 + mi * 16 + l28;
#pragma unroll
    for (int half = 0; half < 2; half++) {
      int row = row0 + half * 8;
      float* crow = C + (size_t)row * N + bn + wn * 32;
      const float* rrow = (EPI == 3) ? (Res + (size_t)row * N + bn + wn * 32) : nullptr;
#pragma unroll
      for (int nj = 0; nj < 4; nj++) {
        int col = nj * 8 + 2 * l4;
        float v0 = acc[mi][nj][half * 2 + 0];
        float v1 = acc[mi][nj][half * 2 + 1];
        if (EPI >= 1) {
          v0 += bias[bn + wn * 32 + col];
          v1 += bias[bn + wn * 32 + col + 1];
        }
        if (EPI == 2) {  // gelu, then pre-round for the consuming GEMM
          v0 = ftf32(0.5f * v0 * (1.f + erff(v0 * 0.70710678118654752f)));
          v1 = ftf32(0.5f * v1 * (1.f + erff(v1 * 0.70710678118654752f)));
        }
        if (EPI == 3) { v0 += rrow[col]; v1 += rrow[col + 1]; }
        *(float2*)(crow + col) = make_float2(v0, v1);
      }
    }
  }
}

// ---------------- structured attention (output pre-rounded to tf32) ----------------
__global__ __launch_bounds__(256) void attn_kernel(const float* __restrict__ qkv,
                                                   float* __restrict__ O) {
  const int fi = blockIdx.x >> 1, qt = blockIdx.x & 1;
  const int h = blockIdx.y, b = blockIdx.z;
  const int fs = fi * BLK;
  const int q0 = fs + qt * 64;
  const int nE = (fi > 0) ? (1 + 17 * (fi + 1)) : 17;
  const int nK = 128 + nE;
  const float* base = qkv + (size_t)b * SEQL * 1536;

  __shared__ __align__(16) float Qs[64][68];
  __shared__ __align__(16) float Ks[64][36];
  __shared__ __align__(16) float Vs[32][68];
  __shared__ __align__(16) float Ps[32][68];
  __shared__ float m_s[64], l_s[64], al_s[64];

  const int tid = threadIdx.x;
  {
    int qr = tid >> 2;
    int c4 = tid & 3;
    const float* qrow = base + (size_t)(q0 + qr) * 1536 + h * 64;
#pragma unroll
    for (int j = 0; j < 4; j++) {
      int d = (c4 * 4 + j) * 4;
      float4 v = *(const float4*)(qrow + d);
      Qs[d + 0][qr] = v.x * 0.125f; Qs[d + 1][qr] = v.y * 0.125f;
      Qs[d + 2][qr] = v.z * 0.125f; Qs[d + 3][qr] = v.w * 0.125f;
    }
  }
  if (tid < 64) { m_s[tid] = -1e30f; l_s[tid] = 0.f; }

  const int tx = tid & 15, ty = tid >> 4;
  float Oa[4][4];
#pragma unroll
  for (int i = 0; i < 4; i++)
#pragma unroll
    for (int j = 0; j < 4; j++) Oa[i][j] = 0.f;

  const int nCh = (nK + 31) / 32;
  for (int ch = 0; ch < nCh; ch++) {
    const int kb = ch * 32;
    __syncthreads();
    {
      int kr = tid >> 3;
      int c2 = tid & 7;
      int t = kb + kr;
      int pos;
      if (t >= nK) pos = fs;
      else if (t < 128) pos = fs + t;
      else {
        int e = t - 128;
        if (fi > 0) {
          if (e == 0) pos = fs - 1;
          else { int e2 = e - 1; pos = (e2 / 17) * BLK + 128 + (e2 % 17); }
        } else pos = 128 + e;
      }
      const float* krow = base + (size_t)pos * 1536 + 512 + h * 64;
      const float* vrow = base + (size_t)pos * 1536 + 1024 + h * 64;
#pragma unroll
      for (int j = 0; j < 2; j++) {
        int d = (c2 * 2 + j) * 4;
        float4 kv = *(const float4*)(krow + d);
        Ks[d + 0][kr] = kv.x; Ks[d + 1][kr] = kv.y; Ks[d + 2][kr] = kv.z; Ks[d + 3][kr] = kv.w;
        float4 vv = *(const float4*)(vrow + d);
        *(float4*)(&Vs[kr][d]) = vv;
      }
    }
    __syncthreads();
    float sreg[4][2];
#pragma unroll
    for (int i = 0; i < 4; i++) { sreg[i][0] = 0.f; sreg[i][1] = 0.f; }
#pragma unroll
    for (int d = 0; d < 64; d++) {
      float qv[4];
      *(float4*)qv = *(const float4*)(&Qs[d][ty * 4]);
      float k0 = Ks[d][tx * 2], k1 = Ks[d][tx * 2 + 1];
#pragma unroll
      for (int i = 0; i < 4; i++) {
        sreg[i][0] = fmaf(qv[i], k0, sreg[i][0]);
        sreg[i][1] = fmaf(qv[i], k1, sreg[i][1]);
      }
    }
#pragma unroll
    for (int j = 0; j < 2; j++) {
      int t = kb + tx * 2 + j;
      bool valid = (t < nK);
#pragma unroll
      for (int i = 0; i < 4; i++)
        Ps[tx * 2 + j][ty * 4 + i] = valid ? sreg[i][j] : -1e30f;
    }
    __syncthreads();
    if (tid < 64) {
      float mo = m_s[tid];
      float mc = -1e30f;
#pragma unroll
      for (int kk = 0; kk < 32; kk++) mc = fmaxf(mc, Ps[kk][tid]);
      float mn = fmaxf(mo, mc);
      float al = expf(mo - mn);
      float ls = 0.f;
#pragma unroll
      for (int kk = 0; kk < 32; kk++) {
        float p = expf(Ps[kk][tid] - mn);
        Ps[kk][tid] = p;
        ls += p;
      }
      m_s[tid] = mn;
      l_s[tid] = l_s[tid] * al + ls;
      al_s[tid] = al;
    }
    __syncthreads();
#pragma unroll
    for (int i = 0; i < 4; i++) {
      float al = al_s[ty * 4 + i];
#pragma unroll
      for (int j = 0; j < 4; j++) Oa[i][j] *= al;
    }
#pragma unroll
    for (int kk = 0; kk < 32; kk++) {
      float pr[4], vr[4];
      *(float4*)pr = *(const float4*)(&Ps[kk][ty * 4]);
      *(float4*)vr = *(const float4*)(&Vs[kk][tx * 4]);
#pragma unroll
      for (int i = 0; i < 4; i++)
#pragma unroll
        for (int j = 0; j < 4; j++) Oa[i][j] = fmaf(pr[i], vr[j], Oa[i][j]);
    }
  }
#pragma unroll
  for (int i = 0; i < 4; i++) {
    int q = ty * 4 + i;
    float inv = 1.f / l_s[q];
    float* orow = O + (size_t)(b * SEQL + q0 + q) * WID + h * 64 + tx * 4;
    float4 ov = make_float4(ftf32(Oa[i][0] * inv), ftf32(Oa[i][1] * inv),
                            ftf32(Oa[i][2] * inv), ftf32(Oa[i][3] * inv));
    *(float4*)orow = ov;
  }
}

// ---------------- non-frame rows: attention output == V (pre-rounded) ----------------
__global__ void copyv_kernel() {
  int idx = blockIdx.x * 256 + threadIdx.x;
  if (idx >= NB * NFR * 18 * WID) return;
  int c = idx & 511;
  int rid = idx >> 9;
  int b = rid / (NFR * 18);
  int rr = rid % (NFR * 18);
  int fi = rr / 18, r = 128 + rr % 18;
  size_t srow = (size_t)b * SEQL + fi * BLK + r;
  g_o[srow * WID + c] = ftf32(g_qkv[srow * 1536 + 1024 + c]);
}

// ---------------- gather frame-token rows for the prediction head (pre-rounded) ----------------
__global__ void gather_kernel() {
  int idx = blockIdx.x * 256 + threadIdx.x;
  if (idx >= MHEAD * WID) return;
  int c = idx & 511, rid = idx >> 9;
  int b = rid / 1536, m = rid % 1536;
  int s = (m >> 7) * BLK + (m & 127);
  g_hf[(size_t)rid * WID + c] = ftf32(g_h[(size_t)(b * SEQL + s) * WID + c]);
}

// ---------------- launch ----------------
extern "C" void kernel_launch(void* const* d_in, const int* in_sizes, int n_in,
                              void* d_out, int out_size) {
  const float* x     = (const float*)d_in[0];
  const float* f     = (const float*)d_in[1];
  const float* delim = (const float*)d_in[2];
  const float* ln1s  = (const float*)d_in[3];
  const float* ln1b  = (const float*)d_in[4];
  const float* wqkv  = (const float*)d_in[5];
  const float* bqkv  = (const float*)d_in[6];
  const float* wout  = (const float*)d_in[7];
  const float* bout  = (const float*)d_in[8];
  const float* ln2s  = (const float*)d_in[9];
  const float* ln2b  = (const float*)d_in[10];
  const float* wfc   = (const float*)d_in[11];
  const float* bfc   = (const float*)d_in[12];
  const float* wproj = (const float*)d_in[13];
  const float* bproj = (const float*)d_in[14];
  const float* whead = (const float*)d_in[15];
  float* out = (float*)d_out;

  float *h, *a, *qkv, *o, *mlp, *hf, *w;
  cudaGetSymbolAddress((void**)&h, g_h);
  cudaGetSymbolAddress((void**)&a, g_a);
  cudaGetSymbolAddress((void**)&qkv, g_qkv);
  cudaGetSymbolAddress((void**)&o, g_o);
  cudaGetSymbolAddress((void**)&mlp, g_mlp);
  cudaGetSymbolAddress((void**)&hf, g_hf);
  cudaGetSymbolAddress((void**)&w, g_w);

  // pre-round all weights to tf32 (once per call; bit-exact with per-load cvt)
  {
    int n;
    n = NLAYER * 1536 * 512 / 4;
    round_w_kernel<<<(n + 255) / 256, 256>>>(wqkv, w + W_QKV, n);
    n = NLAYER * 512 * 512 / 4;
    round_w_kernel<<<(n + 255) / 256, 256>>>(wout, w + W_OUT, n);
    n = NLAYER * 2048 * 512 / 4;
    round_w_kernel<<<(n + 255) / 256, 256>>>(wfc, w + W_FC, n);
    n = NLAYER * 512 * 2048 / 4;
    round_w_kernel<<<(n + 255) / 256, 256>>>(wproj, w + W_PROJ, n);
    n = 1024 * 512 / 4;
    round_w_kernel<<<(n + 255) / 256, 256>>>(whead, w + W_HEAD, n);
  }

  build_h_kernel<<<MPAD, 256>>>(x, f, delim);

  for (int l = 0; l < NLAYER; l++) {
    ln_kernel<<<MROWS, 256>>>(h, ln1s + l * WID, ln1b + l * WID, a);
    gemm_tc<1><<<dim3(1536 / 128, MPAD / 128), 256>>>(
        a, w + W_QKV + (size_t)l * 1536 * WID, bqkv + l * 1536, nullptr, qkv, 1536, WID);
    attn_kernel<<<dim3(NFR * 2, NH, NB), 256>>>(qkv, o);
    copyv_kernel<<<(NB * NFR * 18 * WID + 255) / 256, 256>>>();
    gemm_tc<3><<<dim3(WID / 128, MPAD / 128), 256>>>(
        o, w + W_OUT + (size_t)l * WID * WID, bout + l * WID, h, h, WID, WID);
    ln_kernel<<<MROWS, 256>>>(h, ln2s + l * WID, ln2b + l * WID, a);
    gemm_tc<2><<<dim3(2048 / 128, MPAD / 128), 256>>>(
        a, w + W_FC + (size_t)l * 2048 * WID, bfc + l * 2048, nullptr, mlp, 2048, WID);
    gemm_tc<3><<<dim3(WID / 128, MPAD / 128), 256>>>(
        mlp, w + W_PROJ + (size_t)l * WID * 2048, bproj + l * WID, h, h, WID, 2048);
  }

  gather_kernel<<<(MHEAD * WID + 255) / 256, 256>>>();
  gemm_tc<0><<<dim3(1024 / 128, MHEAD / 128), 256>>>(
      hf, w + W_HEAD, nullptr, nullptr, out, 1024, WID);
}